// round 11
// baseline (speedup 1.0000x reference)
#include <cuda_runtime.h>
#include <cstdint>

typedef unsigned long long ULL;

// ---------- packed fp32x2 helpers ----------
__device__ __forceinline__ void ffma2(ULL &d, ULL a, ULL b) {
    asm("fma.rn.f32x2 %0, %1, %2, %0;" : "+l"(d) : "l"(a), "l"(b));
}
__device__ __forceinline__ float2 unpack2(ULL v) {
    float2 f; asm("mov.b64 {%0,%1}, %2;" : "=f"(f.x), "=f"(f.y) : "l"(v)); return f;
}
__device__ __forceinline__ ULL pack2(float lo, float hi) {
    ULL r; asm("mov.b64 %0, {%1,%2};" : "=l"(r) : "f"(lo), "f"(hi)); return r;
}

// ---------- activations: single-MUFU tanh ----------
__device__ __forceinline__ float tanh_ap(float x) {
    float r; asm("tanh.approx.f32 %0, %1;" : "=f"(r) : "f"(x)); return r;
}
__device__ __forceinline__ float sig_ap(float x) {
    return fmaf(0.5f, tanh_ap(0.5f * x), 0.5f);
}

// ---------- tf32 rounding ----------
__device__ __forceinline__ float tf32r(float x) {
    uint32_t r; asm("cvt.rna.tf32.f32 %0, %1;" : "=r"(r) : "f"(x));
    return __uint_as_float(r);
}

// ---------- bf16 pack: d = {hi=a_hi, lo=a_lo} ----------
__device__ __forceinline__ uint32_t bf16x2(float hi, float lo) {
    uint32_t r; asm("cvt.rn.bf16x2.f32 %0, %1, %2;" : "=r"(r) : "f"(hi), "f"(lo));
    return r;
}
__device__ __forceinline__ float bf16_to_f32(uint16_t v) {
    return __uint_as_float(((uint32_t)v) << 16);
}

// ---------- cp.async ----------
__device__ __forceinline__ void cp16(uint32_t dst_smem, const void* src) {
    asm volatile("cp.async.cg.shared.global [%0], [%1], 16;" :: "r"(dst_smem), "l"(src) : "memory");
}
__device__ __forceinline__ void cp8(uint32_t dst_smem, const void* src) {
    asm volatile("cp.async.ca.shared.global [%0], [%1], 8;" :: "r"(dst_smem), "l"(src) : "memory");
}
__device__ __forceinline__ void cp_commit() { asm volatile("cp.async.commit_group;"); }
__device__ __forceinline__ void cp_wait0()  { asm volatile("cp.async.wait_group 0;" ::: "memory"); }
__device__ __forceinline__ void cp_wait1()  { asm volatile("cp.async.wait_group 1;" ::: "memory"); }

// ---------- constants ----------
constexpr int B = 512, T = 512;
constexpr long BT = (long)B * T;
constexpr int RC = 4;

// ---------- scratch ----------
__device__ __align__(16) float    g_h0T[128 * BT];   // layer-0 out (tf32-rounded), [k][b*T+t]
__device__ __align__(16) uint16_t g_xp1h[BT * 512];  // layer-1 preacts, bf16 [b*T+t][n]
__device__ __align__(16) float    g_BtT[128 * 512];  // Wih_l1^T (tf32-rounded) [k][n]
__device__ float g_pooled[B * 128];

// =======================================================================
// Layer-0 biLSTM (R5/R7-exact, PROTECTED). grid (128, 2), block 256, 2 CTAs/SM.
// =======================================================================
__global__ __launch_bounds__(256, 2) void lstm_l0(
    const float* __restrict__ x,
    const float* __restrict__ Wih_f, const float* __restrict__ Whh_f, const float* __restrict__ b_f,
    const float* __restrict__ Wih_b, const float* __restrict__ Whh_b, const float* __restrict__ b_b)
{
    const int dir = blockIdx.y;
    const int b0  = blockIdx.x * RC;
    const int tid = threadIdx.x;
    const int u   = tid >> 2;
    const int g   = tid & 3;
    const int row = g * 64 + u;

    const float* Wih = dir ? Wih_b : Wih_f;
    const float* Whh = dir ? Whh_b : Whh_f;
    const float* bb  = dir ? b_b   : b_f;

    __shared__ __align__(16) float h_s[2][RC * 64];
    __shared__ __align__(16) float4 x_s[2][RC];
    __shared__ __align__(16) float hist[RC][64][36];

    ULL w2[32];
    {
        const ULL* wp = (const ULL*)(Whh + row * 64);
        #pragma unroll
        for (int i = 0; i < 32; i++) w2[i] = wp[i];
    }
    const float4 wih = *(const float4*)(Wih + row * 4);
    const float bias = bb[row];

    const int lane = tid & 31;
    const int qb   = lane & ~3;

    for (int i = tid; i < RC * 64; i += 256) h_s[0][i] = 0.f;
    if (tid < RC) {
        const int t0 = dir ? (T - 1) : 0;
        x_s[0][tid] = *(const float4*)(x + ((long)(b0 + tid) * T + t0) * 4);
    }
    __syncthreads();

    float c[RC] = {0.f, 0.f, 0.f, 0.f};
    int p = 0;

    for (int s = 0; s < T; s++) {
        const int t = dir ? (T - 1 - s) : s;
        if (tid < RC) {
            const int sn = (s + 1 < T) ? s + 1 : s;
            const int tn = dir ? (T - 1 - sn) : sn;
            x_s[p ^ 1][tid] = *(const float4*)(x + ((long)(b0 + tid) * T + tn) * 4);
        }

        float pre[RC];
        #pragma unroll
        for (int j = 0; j < RC; j++) {
            ULL a0 = 0, a1 = 0;
            const ulonglong2* h4 = (const ulonglong2*)(h_s[p] + j * 64);
            #pragma unroll
            for (int k = 0; k < 16; k++) {
                ulonglong2 hv = h4[k];
                ffma2(a0, w2[2 * k],     hv.x);
                ffma2(a1, w2[2 * k + 1], hv.y);
            }
            const float2 f0 = unpack2(a0), f1 = unpack2(a1);
            const float4 xv = x_s[p][j];
            pre[j] = f0.x + f0.y + f1.x + f1.y + bias
                   + wih.x * xv.x + wih.y * xv.y + wih.z * xv.z + wih.w * xv.w;
        }

        #pragma unroll
        for (int j = 0; j < RC; j++) {
            const float act = (g == 2) ? tanh_ap(pre[j]) : sig_ap(pre[j]);
            const float iv = __shfl_sync(0xffffffffu, act, qb + 0);
            const float fv = __shfl_sync(0xffffffffu, act, qb + 1);
            const float gv = __shfl_sync(0xffffffffu, act, qb + 2);
            const float ov = __shfl_sync(0xffffffffu, act, qb + 3);
            c[j] = fmaf(fv, c[j], iv * gv);
            const float h = ov * tanh_ap(c[j]);
            if (g == 0) {
                h_s[p ^ 1][j * 64 + u] = h;
                hist[j][u][t & 31] = h;
            }
        }
        p ^= 1;
        __syncthreads();

        if ((s & 31) == 31) {
            const int tbase = t & ~31;
            #pragma unroll
            for (int w = 0; w < 8; w++) {
                const int e   = tid + w * 256;
                const int tw4 = e & 7;
                const int ju  = e >> 3;
                const int j   = ju >> 6, uu = ju & 63;
                float4 v = *(const float4*)(&hist[j][uu][tw4 * 4]);
                v.x = tf32r(v.x); v.y = tf32r(v.y); v.z = tf32r(v.z); v.w = tf32r(v.w);
                *(float4*)(g_h0T + (long)(dir * 64 + uu) * BT + (long)(b0 + j) * T + tbase + tw4 * 4) = v;
            }
            __syncthreads();
        }
    }
}

// =======================================================================
// Prep: g_BtT[k][n] = tf32(Wih_l1[n][k])   (n = dir*256 + gate_row)
// =======================================================================
__global__ void prep_btT(const float* __restrict__ Wf, const float* __restrict__ Wb)
{
    const int idx = blockIdx.x * 512 + threadIdx.x;   // 65536
    const int k = idx >> 9, n = idx & 511;
    const float* W = (n & 256) ? Wb : Wf;
    g_BtT[idx] = tf32r(W[(n & 255) * 128 + k]);
}

// =======================================================================
// xp1 GEMM via tf32 mma.sync.m16n8k8, 3-stage cp.async pipeline.
// GRID SWAPPED: n = blockIdx.x (4), m = blockIdx.y (2048) -> 4 consecutive
// CTAs share the same A tile -> A is L2-resident (A DRAM read 537->134MB).
// Output written as bf16 (write traffic 537->268MB).
// grid (4, 2048), blk 256, 2 CTAs/SM (104.4KB smem/CTA).
// =======================================================================
constexpr int FP = 136;
constexpr int KS = 32;
constexpr int SLAB = KS * FP;
constexpr int STG_F = 2 * SLAB;
constexpr int SMEM_GEMM = 3 * STG_F * 4;      // 104448 B

__global__ __launch_bounds__(256, 2) void gemm_xp1(
    const float* __restrict__ bias_f, const float* __restrict__ bias_b)
{
    extern __shared__ float sm[];   // [stage][{A,B}][KS][FP]
    const uint32_t smB = (uint32_t)__cvta_generic_to_shared(sm);
    const int tid  = threadIdx.x;
    const int lane = tid & 31;
    const int wid  = tid >> 5;
    const int g    = lane >> 2;
    const int cc   = lane & 3;
    const int wm   = (wid & 3) * 32;
    const int wn   = (wid >> 2) * 64;
    const long m0 = (long)blockIdx.y * 128;   // m from y (slow index)
    const int  n0 = blockIdx.x * 128;         // n from x (fast index)

    float acc[2][8][4];
    #pragma unroll
    for (int i = 0; i < 2; i++)
        #pragma unroll
        for (int j = 0; j < 8; j++)
            #pragma unroll
            for (int q = 0; q < 4; q++) acc[i][j][q] = 0.f;

    const int lk  = tid >> 5;
    const int lm4 = (tid & 31) * 4;

    auto load_slab = [&](int buf, int kc) {
        const long kg = (long)kc * KS;
        const uint32_t abase = smB + (uint32_t)(buf * STG_F) * 4;
        const uint32_t bbase = abase + (uint32_t)SLAB * 4;
        #pragma unroll
        for (int i = 0; i < 4; i++) {
            const int k = lk + i * 8;
            cp16(abase + (uint32_t)(k * FP + lm4) * 4, g_h0T + (kg + k) * BT + m0 + lm4);
        }
        #pragma unroll
        for (int i = 0; i < 4; i++) {
            const int k = lk + i * 8;
            cp16(bbase + (uint32_t)(k * FP + lm4) * 4, g_BtT + (kg + k) * 512 + n0 + lm4);
        }
    };

    load_slab(0, 0); cp_commit();
    load_slab(1, 1); cp_commit();

    for (int kc = 0; kc < 4; kc++) {
        if (kc == 3) cp_wait0(); else cp_wait1();
        __syncthreads();
        if (kc + 2 < 4) { load_slab((kc + 2) % 3, kc + 2); cp_commit(); }

        const float* As = sm + (kc % 3) * STG_F;
        const float* Bs = As + SLAB;
        #pragma unroll
        for (int kk = 0; kk < KS / 8; kk++) {
            const float* abase = As + (kk * 8 + cc) * FP + wm + g;
            uint32_t a0[2], a1[2], a2[2], a3[2];
            #pragma unroll
            for (int i = 0; i < 2; i++) {
                const float* ap = abase + 16 * i;
                a0[i] = __float_as_uint(ap[0]);
                a1[i] = __float_as_uint(ap[8]);
                a2[i] = __float_as_uint(ap[4 * FP]);
                a3[i] = __float_as_uint(ap[4 * FP + 8]);
            }
            const float* bbase = Bs + (kk * 8 + cc) * FP + wn + g;
            uint32_t b0[8], b1[8];
            #pragma unroll
            for (int j = 0; j < 8; j++) {
                b0[j] = __float_as_uint(bbase[8 * j]);
                b1[j] = __float_as_uint(bbase[8 * j + 4 * FP]);
            }
            #pragma unroll
            for (int i = 0; i < 2; i++)
                #pragma unroll
                for (int j = 0; j < 8; j++) {
                    asm("mma.sync.aligned.m16n8k8.row.col.f32.tf32.tf32.f32 "
                        "{%0,%1,%2,%3}, {%4,%5,%6,%7}, {%8,%9}, {%0,%1,%2,%3};"
                        : "+f"(acc[i][j][0]), "+f"(acc[i][j][1]),
                          "+f"(acc[i][j][2]), "+f"(acc[i][j][3])
                        : "r"(a0[i]), "r"(a1[i]), "r"(a2[i]), "r"(a3[i]),
                          "r"(b0[j]), "r"(b1[j]));
                }
        }
    }

    // epilogue: + bias, pack bf16x2, u32 stores
    const float* bp = (n0 & 256) ? bias_b : bias_f;
    float bn0[8], bn1[8];
    #pragma unroll
    for (int j = 0; j < 8; j++) {
        const int n = ((n0 & 255) + wn + 8 * j + cc * 2);
        bn0[j] = bp[n & 255];
        bn1[j] = bp[(n + 1) & 255];
    }
    #pragma unroll
    for (int i = 0; i < 2; i++) {
        const long mrow = m0 + wm + 16 * i + g;
        uint16_t* r0 = g_xp1h + mrow * 512;
        uint16_t* r1 = r0 + 8 * 512;
        #pragma unroll
        for (int j = 0; j < 8; j++) {
            const int n = n0 + wn + 8 * j + cc * 2;
            *(uint32_t*)(r0 + n) = bf16x2(acc[i][j][1] + bn1[j], acc[i][j][0] + bn0[j]);
            *(uint32_t*)(r1 + n) = bf16x2(acc[i][j][3] + bn1[j], acc[i][j][2] + bn0[j]);
        }
    }
}

// =======================================================================
// Layer-1 biLSTM (R8 core, PROTECTED; xp staging now bf16 via 8B cp.async).
// grid (128, 2), block 256, 2 CTAs/SM.
// xp_s layout [buf][j][g][72 u16] (stride 144B): conflict-free lds.u16.
// =======================================================================
__global__ __launch_bounds__(256, 2) void lstm_l1(
    const float* __restrict__ Whh_f, const float* __restrict__ Whh_b)
{
    const int dir = blockIdx.y;
    const int b0  = blockIdx.x * RC;
    const int tid = threadIdx.x;
    const int u   = tid >> 2;
    const int g   = tid & 3;
    const int row = g * 64 + u;
    const float* Whh = dir ? Whh_b : Whh_f;

    __shared__ __align__(16) float h_s[2][RC * 64];
    __shared__ __align__(16) uint16_t xp_s[2][RC][4][72];

    ULL w2[32];
    {
        const ULL* wp = (const ULL*)(Whh + row * 64);
        #pragma unroll
        for (int i = 0; i < 32; i++) w2[i] = wp[i];
    }
    const int lane = tid & 31;
    const int qb   = lane & ~3;

    // staging: thread -> (j_st, g_st, u4_st), 4 bf16 = 8 bytes
    const int j_st  = tid >> 6;
    const int c_st  = tid & 63;          // g_st*16 + grp
    const int g_st  = c_st >> 4;
    const int u4_st = (c_st & 15) * 4;
    const uint32_t xpsB = (uint32_t)__cvta_generic_to_shared(&xp_s[0][0][0][0]);
    const uint32_t st_off = (uint32_t)(((j_st * 4 + g_st) * 72 + u4_st) * 2);
    const uint32_t buf_stride = (uint32_t)(RC * 4 * 72 * 2);
    const uint16_t* xp_src = g_xp1h + (long)(b0 + j_st) * T * 512 + dir * 256 + g_st * 64 + u4_st;

    for (int i = tid; i < RC * 64; i += 256) h_s[0][i] = 0.f;

    float c[RC]    = {0.f, 0.f, 0.f, 0.f};
    float hsum[RC] = {0.f, 0.f, 0.f, 0.f};
    {
        const int t0 = dir ? (T - 1) : 0;
        cp8(xpsB + st_off, xp_src + (long)t0 * 512);
        cp_commit();
        cp_wait0();
    }
    __syncthreads();

    int p = 0;
    for (int s = 0; s < T; s++) {
        if (s + 1 < T) {
            const int tn = dir ? (T - 2 - s) : (s + 1);
            cp8(xpsB + (p ^ 1) * buf_stride + st_off, xp_src + (long)tn * 512);
            cp_commit();
        }

        float pre[RC];
        #pragma unroll
        for (int j = 0; j < RC; j++) {
            ULL a0 = 0, a1 = 0;
            const ulonglong2* h4 = (const ulonglong2*)(h_s[p] + j * 64);
            #pragma unroll
            for (int k = 0; k < 16; k++) {
                ulonglong2 hv = h4[k];
                ffma2(a0, w2[2 * k],     hv.x);
                ffma2(a1, w2[2 * k + 1], hv.y);
            }
            const float2 f0 = unpack2(a0), f1 = unpack2(a1);
            pre[j] = f0.x + f0.y + f1.x + f1.y + bf16_to_f32(xp_s[p][j][g][u]);
        }

        #pragma unroll
        for (int j = 0; j < RC; j++) {
            const float act = (g == 2) ? tanh_ap(pre[j]) : sig_ap(pre[j]);
            const float iv = __shfl_sync(0xffffffffu, act, qb + 0);
            const float fv = __shfl_sync(0xffffffffu, act, qb + 1);
            const float gv = __shfl_sync(0xffffffffu, act, qb + 2);
            const float ov = __shfl_sync(0xffffffffu, act, qb + 3);
            c[j] = fmaf(fv, c[j], iv * gv);
            const float h = ov * tanh_ap(c[j]);
            hsum[j] += h;
            if (g == 0) h_s[p ^ 1][j * 64 + u] = h;
        }
        cp_wait0();
        p ^= 1;
        __syncthreads();
    }

    if (g == 0) {
        #pragma unroll
        for (int j = 0; j < RC; j++)
            g_pooled[(b0 + j) * 128 + dir * 64 + u] = hsum[j];
    }
}

// =======================================================================
__global__ void fc_kernel(const float* __restrict__ fcw, const float* __restrict__ fcb,
                          float* __restrict__ out)
{
    const int gw   = (blockIdx.x * blockDim.x + threadIdx.x) >> 5;
    const int lane = threadIdx.x & 31;
    if (gw >= B) return;
    float sum = 0.f;
    #pragma unroll
    for (int qq = 0; qq < 4; qq++)
        sum += g_pooled[gw * 128 + qq * 32 + lane] * fcw[qq * 32 + lane];
    #pragma unroll
    for (int o = 16; o; o >>= 1) sum += __shfl_xor_sync(0xffffffffu, sum, o);
    if (lane == 0) out[gw] = sum * (1.f / 512.f) + fcb[0];
}

// =======================================================================
extern "C" void kernel_launch(void* const* d_in, const int* in_sizes, int n_in,
                              void* d_out, int out_size)
{
    const float* x     = (const float*)d_in[0];
    const float* Wih0f = (const float*)d_in[1];
    const float* Whh0f = (const float*)d_in[2];
    const float* b0f   = (const float*)d_in[3];
    const float* Wih0b = (const float*)d_in[4];
    const float* Whh0b = (const float*)d_in[5];
    const float* b0b   = (const float*)d_in[6];
    const float* Wih1f = (const float*)d_in[7];
    const float* Whh1f = (const float*)d_in[8];
    const float* b1f   = (const float*)d_in[9];
    const float* Wih1b = (const float*)d_in[10];
    const float* Whh1b = (const float*)d_in[11];
    const float* b1b   = (const float*)d_in[12];
    const float* fcw   = (const float*)d_in[13];
    const float* fcb   = (const float*)d_in[14];

    prep_btT<<<128, 512>>>(Wih1f, Wih1b);
    lstm_l0<<<dim3(B / RC, 2), 256>>>(x, Wih0f, Whh0f, b0f, Wih0b, Whh0b, b0b);
    cudaFuncSetAttribute(gemm_xp1, cudaFuncAttributeMaxDynamicSharedMemorySize, SMEM_GEMM);
    gemm_xp1<<<dim3(4, 2048), 256, SMEM_GEMM>>>(b1f, b1b);
    lstm_l1<<<dim3(B / RC, 2), 256>>>(Whh1f, Whh1b);
    fc_kernel<<<32, 512>>>(fcw, fcb, (float*)d_out);
}

// round 12
// speedup vs baseline: 1.0374x; 1.0374x over previous
#include <cuda_runtime.h>
#include <cstdint>

typedef unsigned long long ULL;

// ---------- packed fp32x2 helpers ----------
__device__ __forceinline__ void ffma2(ULL &d, ULL a, ULL b) {
    asm("fma.rn.f32x2 %0, %1, %2, %0;" : "+l"(d) : "l"(a), "l"(b));
}
__device__ __forceinline__ float2 unpack2(ULL v) {
    float2 f; asm("mov.b64 {%0,%1}, %2;" : "=f"(f.x), "=f"(f.y) : "l"(v)); return f;
}

// ---------- activations: single-MUFU tanh ----------
__device__ __forceinline__ float tanh_ap(float x) {
    float r; asm("tanh.approx.f32 %0, %1;" : "=f"(r) : "f"(x)); return r;
}
__device__ __forceinline__ float sig_ap(float x) {
    return fmaf(0.5f, tanh_ap(0.5f * x), 0.5f);
}

// ---------- tf32 rounding ----------
__device__ __forceinline__ float tf32r(float x) {
    uint32_t r; asm("cvt.rna.tf32.f32 %0, %1;" : "=r"(r) : "f"(x));
    return __uint_as_float(r);
}

// ---------- bf16 ----------
__device__ __forceinline__ uint32_t bf16x2(float hi, float lo) {
    uint32_t r; asm("cvt.rn.bf16x2.f32 %0, %1, %2;" : "=r"(r) : "f"(hi), "f"(lo));
    return r;
}
__device__ __forceinline__ float bf16_to_f32(uint16_t v) {
    return __uint_as_float(((uint32_t)v) << 16);
}

// ---------- cp.async ----------
__device__ __forceinline__ void cp16(uint32_t dst_smem, const void* src) {
    asm volatile("cp.async.cg.shared.global [%0], [%1], 16;" :: "r"(dst_smem), "l"(src) : "memory");
}
__device__ __forceinline__ void cp8(uint32_t dst_smem, const void* src) {
    asm volatile("cp.async.ca.shared.global [%0], [%1], 8;" :: "r"(dst_smem), "l"(src) : "memory");
}
__device__ __forceinline__ void cp_commit() { asm volatile("cp.async.commit_group;"); }
__device__ __forceinline__ void cp_wait0()  { asm volatile("cp.async.wait_group 0;" ::: "memory"); }
__device__ __forceinline__ void cp_wait1()  { asm volatile("cp.async.wait_group 1;" ::: "memory"); }

// ---------- constants ----------
constexpr int B = 512, T = 512;
constexpr long BT = (long)B * T;

// ---------- scratch ----------
__device__ __align__(16) float    g_h0T[128 * BT];   // layer-0 out (tf32), [k][b*T+t]
__device__ __align__(16) uint16_t g_xp1h[BT * 512];  // layer-1 preacts, bf16 [b*T+t][n]
__device__ __align__(16) float    g_BtT[128 * 512];  // Wih_l1^T (tf32) [k][n]
__device__ float g_pooled[B * 128];

// ---------- load-balance mapping: grid (148, 2); SM pairing via bid%148 ----
// dir0: x<68 -> RC4 (b0=4x), else RC3 (b0=272+3(x-68))
// dir1: x<80 -> RC3 (b0=3x), else RC4 (b0=240+4(x-80))
// => every SM hosts 4+3=7 or 3+3=6 row-units (never 8).
__device__ __forceinline__ bool map_big(int x, int dir) {
    return dir == 0 ? (x < 68) : (x >= 80);
}
__device__ __forceinline__ int map_b0(int x, int dir, bool big) {
    return dir == 0 ? (big ? x * 4 : 272 + (x - 68) * 3)
                    : (big ? 240 + (x - 80) * 4 : x * 3);
}

// =======================================================================
// Layer-0 biLSTM core (R5/R8-protected structure), templated on row count.
// =======================================================================
template <int RCT>
__device__ __forceinline__ void l0_body(
    int dir, int b0, int tid,
    const float* __restrict__ x,
    const float* __restrict__ Wih, const float* __restrict__ Whh, const float* __restrict__ bb,
    float (&h_s)[2][4 * 64], float4 (&x_s)[2][4], float (&hist)[4][64][36])
{
    const int u   = tid >> 2;
    const int g   = tid & 3;
    const int row = g * 64 + u;

    ULL w2[32];
    {
        const ULL* wp = (const ULL*)(Whh + row * 64);
        #pragma unroll
        for (int i = 0; i < 32; i++) w2[i] = wp[i];
    }
    const float4 wih = *(const float4*)(Wih + row * 4);
    const float bias = bb[row];

    const int lane = tid & 31;
    const int qb   = lane & ~3;

    for (int i = tid; i < RCT * 64; i += 256) h_s[0][i] = 0.f;
    if (tid < RCT) {
        const int t0 = dir ? (T - 1) : 0;
        x_s[0][tid] = *(const float4*)(x + ((long)(b0 + tid) * T + t0) * 4);
    }
    __syncthreads();

    float c[RCT];
    #pragma unroll
    for (int j = 0; j < RCT; j++) c[j] = 0.f;
    int p = 0;

    for (int s = 0; s < T; s++) {
        const int t = dir ? (T - 1 - s) : s;
        if (tid < RCT) {
            const int sn = (s + 1 < T) ? s + 1 : s;
            const int tn = dir ? (T - 1 - sn) : sn;
            x_s[p ^ 1][tid] = *(const float4*)(x + ((long)(b0 + tid) * T + tn) * 4);
        }

        float pre[RCT];
        #pragma unroll
        for (int j = 0; j < RCT; j++) {
            ULL a0 = 0, a1 = 0;
            const ulonglong2* h4 = (const ulonglong2*)(h_s[p] + j * 64);
            #pragma unroll
            for (int k = 0; k < 16; k++) {
                ulonglong2 hv = h4[k];
                ffma2(a0, w2[2 * k],     hv.x);
                ffma2(a1, w2[2 * k + 1], hv.y);
            }
            const float2 f0 = unpack2(a0), f1 = unpack2(a1);
            const float4 xv = x_s[p][j];
            pre[j] = f0.x + f0.y + f1.x + f1.y + bias
                   + wih.x * xv.x + wih.y * xv.y + wih.z * xv.z + wih.w * xv.w;
        }

        #pragma unroll
        for (int j = 0; j < RCT; j++) {
            const float act = (g == 2) ? tanh_ap(pre[j]) : sig_ap(pre[j]);
            const float iv = __shfl_sync(0xffffffffu, act, qb + 0);
            const float fv = __shfl_sync(0xffffffffu, act, qb + 1);
            const float gv = __shfl_sync(0xffffffffu, act, qb + 2);
            const float ov = __shfl_sync(0xffffffffu, act, qb + 3);
            c[j] = fmaf(fv, c[j], iv * gv);
            const float h = ov * tanh_ap(c[j]);
            if (g == 0) {
                h_s[p ^ 1][j * 64 + u] = h;
                hist[j][u][t & 31] = h;
            }
        }
        p ^= 1;
        __syncthreads();

        if ((s & 31) == 31) {
            const int tbase = t & ~31;
            #pragma unroll
            for (int e = tid; e < RCT * 64 * 8; e += 256) {
                const int tw4 = e & 7;
                const int ju  = e >> 3;
                const int j   = ju >> 6, uu = ju & 63;
                float4 v = *(const float4*)(&hist[j][uu][tw4 * 4]);
                v.x = tf32r(v.x); v.y = tf32r(v.y); v.z = tf32r(v.z); v.w = tf32r(v.w);
                *(float4*)(g_h0T + (long)(dir * 64 + uu) * BT + (long)(b0 + j) * T + tbase + tw4 * 4) = v;
            }
            __syncthreads();
        }
    }
}

__global__ __launch_bounds__(256, 2) void lstm_l0(
    const float* __restrict__ x,
    const float* __restrict__ Wih_f, const float* __restrict__ Whh_f, const float* __restrict__ b_f,
    const float* __restrict__ Wih_b, const float* __restrict__ Whh_b, const float* __restrict__ b_b)
{
    __shared__ __align__(16) float h_s[2][4 * 64];
    __shared__ __align__(16) float4 x_s[2][4];
    __shared__ __align__(16) float hist[4][64][36];

    const int xw  = blockIdx.x;
    const int dir = blockIdx.y;
    const bool big = map_big(xw, dir);
    const int b0   = map_b0(xw, dir, big);
    const int tid = threadIdx.x;

    const float* Wih = dir ? Wih_b : Wih_f;
    const float* Whh = dir ? Whh_b : Whh_f;
    const float* bb  = dir ? b_b   : b_f;

    if (big) l0_body<4>(dir, b0, tid, x, Wih, Whh, bb, h_s, x_s, hist);
    else     l0_body<3>(dir, b0, tid, x, Wih, Whh, bb, h_s, x_s, hist);
}

// =======================================================================
// Prep: g_BtT[k][n] = tf32(Wih_l1[n][k])   (n = dir*256 + gate_row)
// =======================================================================
__global__ void prep_btT(const float* __restrict__ Wf, const float* __restrict__ Wb)
{
    const int idx = blockIdx.x * 512 + threadIdx.x;   // 65536
    const int k = idx >> 9, n = idx & 511;
    const float* W = (n & 256) ? Wb : Wf;
    g_BtT[idx] = tf32r(W[(n & 255) * 128 + k]);
}

// =======================================================================
// xp1 GEMM (R11-exact): tf32 mma.sync, 3-stage cp.async, n-fast grid,
// bf16 output. grid (4, 2048), blk 256, 2 CTAs/SM.
// =======================================================================
constexpr int FP = 136;
constexpr int KS = 32;
constexpr int SLAB = KS * FP;
constexpr int STG_F = 2 * SLAB;
constexpr int SMEM_GEMM = 3 * STG_F * 4;      // 104448 B

__global__ __launch_bounds__(256, 2) void gemm_xp1(
    const float* __restrict__ bias_f, const float* __restrict__ bias_b)
{
    extern __shared__ float sm[];
    const uint32_t smB = (uint32_t)__cvta_generic_to_shared(sm);
    const int tid  = threadIdx.x;
    const int lane = tid & 31;
    const int wid  = tid >> 5;
    const int g    = lane >> 2;
    const int cc   = lane & 3;
    const int wm   = (wid & 3) * 32;
    const int wn   = (wid >> 2) * 64;
    const long m0 = (long)blockIdx.y * 128;
    const int  n0 = blockIdx.x * 128;

    float acc[2][8][4];
    #pragma unroll
    for (int i = 0; i < 2; i++)
        #pragma unroll
        for (int j = 0; j < 8; j++)
            #pragma unroll
            for (int q = 0; q < 4; q++) acc[i][j][q] = 0.f;

    const int lk  = tid >> 5;
    const int lm4 = (tid & 31) * 4;

    auto load_slab = [&](int buf, int kc) {
        const long kg = (long)kc * KS;
        const uint32_t abase = smB + (uint32_t)(buf * STG_F) * 4;
        const uint32_t bbase = abase + (uint32_t)SLAB * 4;
        #pragma unroll
        for (int i = 0; i < 4; i++) {
            const int k = lk + i * 8;
            cp16(abase + (uint32_t)(k * FP + lm4) * 4, g_h0T + (kg + k) * BT + m0 + lm4);
        }
        #pragma unroll
        for (int i = 0; i < 4; i++) {
            const int k = lk + i * 8;
            cp16(bbase + (uint32_t)(k * FP + lm4) * 4, g_BtT + (kg + k) * 512 + n0 + lm4);
        }
    };

    load_slab(0, 0); cp_commit();
    load_slab(1, 1); cp_commit();

    for (int kc = 0; kc < 4; kc++) {
        if (kc == 3) cp_wait0(); else cp_wait1();
        __syncthreads();
        if (kc + 2 < 4) { load_slab((kc + 2) % 3, kc + 2); cp_commit(); }

        const float* As = sm + (kc % 3) * STG_F;
        const float* Bs = As + SLAB;
        #pragma unroll
        for (int kk = 0; kk < KS / 8; kk++) {
            const float* abase = As + (kk * 8 + cc) * FP + wm + g;
            uint32_t a0[2], a1[2], a2[2], a3[2];
            #pragma unroll
            for (int i = 0; i < 2; i++) {
                const float* ap = abase + 16 * i;
                a0[i] = __float_as_uint(ap[0]);
                a1[i] = __float_as_uint(ap[8]);
                a2[i] = __float_as_uint(ap[4 * FP]);
                a3[i] = __float_as_uint(ap[4 * FP + 8]);
            }
            const float* bbase = Bs + (kk * 8 + cc) * FP + wn + g;
            uint32_t b0[8], b1[8];
            #pragma unroll
            for (int j = 0; j < 8; j++) {
                b0[j] = __float_as_uint(bbase[8 * j]);
                b1[j] = __float_as_uint(bbase[8 * j + 4 * FP]);
            }
            #pragma unroll
            for (int i = 0; i < 2; i++)
                #pragma unroll
                for (int j = 0; j < 8; j++) {
                    asm("mma.sync.aligned.m16n8k8.row.col.f32.tf32.tf32.f32 "
                        "{%0,%1,%2,%3}, {%4,%5,%6,%7}, {%8,%9}, {%0,%1,%2,%3};"
                        : "+f"(acc[i][j][0]), "+f"(acc[i][j][1]),
                          "+f"(acc[i][j][2]), "+f"(acc[i][j][3])
                        : "r"(a0[i]), "r"(a1[i]), "r"(a2[i]), "r"(a3[i]),
                          "r"(b0[j]), "r"(b1[j]));
                }
        }
    }

    const float* bp = (n0 & 256) ? bias_b : bias_f;
    float bn0[8], bn1[8];
    #pragma unroll
    for (int j = 0; j < 8; j++) {
        const int n = ((n0 & 255) + wn + 8 * j + cc * 2);
        bn0[j] = bp[n & 255];
        bn1[j] = bp[(n + 1) & 255];
    }
    #pragma unroll
    for (int i = 0; i < 2; i++) {
        const long mrow = m0 + wm + 16 * i + g;
        uint16_t* r0 = g_xp1h + mrow * 512;
        uint16_t* r1 = r0 + 8 * 512;
        #pragma unroll
        for (int j = 0; j < 8; j++) {
            const int n = n0 + wn + 8 * j + cc * 2;
            *(uint32_t*)(r0 + n) = bf16x2(acc[i][j][1] + bn1[j], acc[i][j][0] + bn0[j]);
            *(uint32_t*)(r1 + n) = bf16x2(acc[i][j][3] + bn1[j], acc[i][j][2] + bn0[j]);
        }
    }
}

// =======================================================================
// Layer-1 biLSTM core (R8-protected structure + bf16 xp), templated rows.
// =======================================================================
template <int RCT>
__device__ __forceinline__ void l1_body(
    int dir, int b0, int tid,
    const float* __restrict__ Whh,
    float (&h_s)[2][4 * 64], uint16_t (&xp_s)[2][4][4][72])
{
    const int u   = tid >> 2;
    const int g   = tid & 3;
    const int row = g * 64 + u;

    ULL w2[32];
    {
        const ULL* wp = (const ULL*)(Whh + row * 64);
        #pragma unroll
        for (int i = 0; i < 32; i++) w2[i] = wp[i];
    }
    const int lane = tid & 31;
    const int qb   = lane & ~3;

    const int j_st  = tid >> 6;
    const int c_st  = tid & 63;
    const int g_st  = c_st >> 4;
    const int u4_st = (c_st & 15) * 4;
    const uint32_t xpsB = (uint32_t)__cvta_generic_to_shared(&xp_s[0][0][0][0]);
    const uint32_t st_off = (uint32_t)(((j_st * 4 + g_st) * 72 + u4_st) * 2);
    const uint32_t buf_stride = (uint32_t)(4 * 4 * 72 * 2);
    const uint16_t* xp_src = g_xp1h + (long)(b0 + j_st) * T * 512 + dir * 256 + g_st * 64 + u4_st;
    const bool do_st = (j_st < RCT);

    for (int i = tid; i < RCT * 64; i += 256) h_s[0][i] = 0.f;

    float c[RCT], hsum[RCT];
    #pragma unroll
    for (int j = 0; j < RCT; j++) { c[j] = 0.f; hsum[j] = 0.f; }
    {
        const int t0 = dir ? (T - 1) : 0;
        if (do_st) cp8(xpsB + st_off, xp_src + (long)t0 * 512);
        cp_commit();
        cp_wait0();
    }
    __syncthreads();

    int p = 0;
    for (int s = 0; s < T; s++) {
        if (s + 1 < T) {
            const int tn = dir ? (T - 2 - s) : (s + 1);
            if (do_st) cp8(xpsB + (p ^ 1) * buf_stride + st_off, xp_src + (long)tn * 512);
            cp_commit();
        }

        float pre[RCT];
        #pragma unroll
        for (int j = 0; j < RCT; j++) {
            ULL a0 = 0, a1 = 0;
            const ulonglong2* h4 = (const ulonglong2*)(h_s[p] + j * 64);
            #pragma unroll
            for (int k = 0; k < 16; k++) {
                ulonglong2 hv = h4[k];
                ffma2(a0, w2[2 * k],     hv.x);
                ffma2(a1, w2[2 * k + 1], hv.y);
            }
            const float2 f0 = unpack2(a0), f1 = unpack2(a1);
            pre[j] = f0.x + f0.y + f1.x + f1.y + bf16_to_f32(xp_s[p][j][g][u]);
        }

        #pragma unroll
        for (int j = 0; j < RCT; j++) {
            const float act = (g == 2) ? tanh_ap(pre[j]) : sig_ap(pre[j]);
            const float iv = __shfl_sync(0xffffffffu, act, qb + 0);
            const float fv = __shfl_sync(0xffffffffu, act, qb + 1);
            const float gv = __shfl_sync(0xffffffffu, act, qb + 2);
            const float ov = __shfl_sync(0xffffffffu, act, qb + 3);
            c[j] = fmaf(fv, c[j], iv * gv);
            const float h = ov * tanh_ap(c[j]);
            hsum[j] += h;
            if (g == 0) h_s[p ^ 1][j * 64 + u] = h;
        }
        cp_wait0();
        p ^= 1;
        __syncthreads();
    }

    if (g == 0) {
        #pragma unroll
        for (int j = 0; j < RCT; j++)
            g_pooled[(b0 + j) * 128 + dir * 64 + u] = hsum[j];
    }
}

__global__ __launch_bounds__(256, 2) void lstm_l1(
    const float* __restrict__ Whh_f, const float* __restrict__ Whh_b)
{
    __shared__ __align__(16) float h_s[2][4 * 64];
    __shared__ __align__(16) uint16_t xp_s[2][4][4][72];

    const int xw  = blockIdx.x;
    const int dir = blockIdx.y;
    const bool big = map_big(xw, dir);
    const int b0   = map_b0(xw, dir, big);
    const int tid = threadIdx.x;
    const float* Whh = dir ? Whh_b : Whh_f;

    if (big) l1_body<4>(dir, b0, tid, Whh, h_s, xp_s);
    else     l1_body<3>(dir, b0, tid, Whh, h_s, xp_s);
}

// =======================================================================
__global__ void fc_kernel(const float* __restrict__ fcw, const float* __restrict__ fcb,
                          float* __restrict__ out)
{
    const int gw   = (blockIdx.x * blockDim.x + threadIdx.x) >> 5;
    const int lane = threadIdx.x & 31;
    if (gw >= B) return;
    float sum = 0.f;
    #pragma unroll
    for (int qq = 0; qq < 4; qq++)
        sum += g_pooled[gw * 128 + qq * 32 + lane] * fcw[qq * 32 + lane];
    #pragma unroll
    for (int o = 16; o; o >>= 1) sum += __shfl_xor_sync(0xffffffffu, sum, o);
    if (lane == 0) out[gw] = sum * (1.f / 512.f) + fcb[0];
}

// =======================================================================
extern "C" void kernel_launch(void* const* d_in, const int* in_sizes, int n_in,
                              void* d_out, int out_size)
{
    const float* x     = (const float*)d_in[0];
    const float* Wih0f = (const float*)d_in[1];
    const float* Whh0f = (const float*)d_in[2];
    const float* b0f   = (const float*)d_in[3];
    const float* Wih0b = (const float*)d_in[4];
    const float* Whh0b = (const float*)d_in[5];
    const float* b0b   = (const float*)d_in[6];
    const float* Wih1f = (const float*)d_in[7];
    const float* Whh1f = (const float*)d_in[8];
    const float* b1f   = (const float*)d_in[9];
    const float* Wih1b = (const float*)d_in[10];
    const float* Whh1b = (const float*)d_in[11];
    const float* b1b   = (const float*)d_in[12];
    const float* fcw   = (const float*)d_in[13];
    const float* fcb   = (const float*)d_in[14];

    prep_btT<<<128, 512>>>(Wih1f, Wih1b);
    lstm_l0<<<dim3(148, 2), 256>>>(x, Wih0f, Whh0f, b0f, Wih0b, Whh0b, b0b);
    cudaFuncSetAttribute(gemm_xp1, cudaFuncAttributeMaxDynamicSharedMemorySize, SMEM_GEMM);
    gemm_xp1<<<dim3(4, 2048), 256, SMEM_GEMM>>>(b1f, b1b);
    lstm_l1<<<dim3(148, 2), 256>>>(Whh1f, Whh1b);
    fc_kernel<<<32, 512>>>(fcw, fcb, (float*)d_out);
}

// round 14
// speedup vs baseline: 1.1604x; 1.1186x over previous
#include <cuda_runtime.h>
#include <cstdint>

typedef unsigned long long ULL;

// ---------- packed fp32x2 helpers ----------
__device__ __forceinline__ void ffma2(ULL &d, ULL a, ULL b) {
    asm("fma.rn.f32x2 %0, %1, %2, %0;" : "+l"(d) : "l"(a), "l"(b));
}
__device__ __forceinline__ float2 unpack2(ULL v) {
    float2 f; asm("mov.b64 {%0,%1}, %2;" : "=f"(f.x), "=f"(f.y) : "l"(v)); return f;
}

// ---------- activations: single-MUFU tanh ----------
__device__ __forceinline__ float tanh_ap(float x) {
    float r; asm("tanh.approx.f32 %0, %1;" : "=f"(r) : "f"(x)); return r;
}
__device__ __forceinline__ float sig_ap(float x) {
    return fmaf(0.5f, tanh_ap(0.5f * x), 0.5f);
}

// ---------- bf16 ----------
__device__ __forceinline__ uint32_t bf16x2(float hi, float lo) {
    uint32_t r; asm("cvt.rn.bf16x2.f32 %0, %1, %2;" : "=r"(r) : "f"(hi), "f"(lo));
    return r;
}
__device__ __forceinline__ uint16_t bf16of(float x) {
    uint16_t r; asm("cvt.rn.bf16.f32 %0, %1;" : "=h"(r) : "f"(x));
    return r;
}
__device__ __forceinline__ float bf16_to_f32(uint16_t v) {
    return __uint_as_float(((uint32_t)v) << 16);
}

// ---------- cp.async ----------
__device__ __forceinline__ void cp16(uint32_t dst_smem, const void* src) {
    asm volatile("cp.async.cg.shared.global [%0], [%1], 16;" :: "r"(dst_smem), "l"(src) : "memory");
}
__device__ __forceinline__ void cp8(uint32_t dst_smem, const void* src) {
    asm volatile("cp.async.ca.shared.global [%0], [%1], 8;" :: "r"(dst_smem), "l"(src) : "memory");
}
__device__ __forceinline__ void cp_commit() { asm volatile("cp.async.commit_group;"); }
__device__ __forceinline__ void cp_wait0()  { asm volatile("cp.async.wait_group 0;" ::: "memory"); }
__device__ __forceinline__ void cp_wait1()  { asm volatile("cp.async.wait_group 1;" ::: "memory"); }

// ---------- constants ----------
constexpr int B = 512, T = 512;
constexpr long BT = (long)B * T;

// ---------- scratch ----------
__device__ __align__(16) uint16_t g_h0h[BT * 128];   // layer-0 out bf16, NATURAL [b*T+t][k]
__device__ __align__(16) uint16_t g_xp1h[BT * 512];  // layer-1 preacts bf16 [b*T+t][n]
__device__ __align__(16) uint16_t g_Bth[512 * 128];  // Wih_l1 bf16 [n][k] (n = dir*256+row)
__device__ float g_pooled[B * 128];

// ---------- load-balance mapping: grid (148, 2); SM pairing via bid%148 ----
__device__ __forceinline__ bool map_big(int x, int dir) {
    return dir == 0 ? (x < 68) : (x >= 80);
}
__device__ __forceinline__ int map_b0(int x, int dir, bool big) {
    return dir == 0 ? (big ? x * 4 : 272 + (x - 68) * 3)
                    : (big ? 240 + (x - 80) * 4 : x * 3);
}

// =======================================================================
// Layer-0 biLSTM core (R5/R8-protected structure), templated on row count.
// h written directly as bf16 to natural-layout g_h0h (no hist/transpose).
// =======================================================================
template <int RCT>
__device__ __forceinline__ void l0_body(
    int dir, int b0, int tid,
    const float* __restrict__ x,
    const float* __restrict__ Wih, const float* __restrict__ Whh, const float* __restrict__ bb,
    float (&h_s)[2][4 * 64], float4 (&x_s)[2][4])
{
    const int u   = tid >> 2;
    const int g   = tid & 3;
    const int row = g * 64 + u;

    ULL w2[32];
    {
        const ULL* wp = (const ULL*)(Whh + row * 64);
        #pragma unroll
        for (int i = 0; i < 32; i++) w2[i] = wp[i];
    }
    const float4 wih = *(const float4*)(Wih + row * 4);
    const float bias = bb[row];

    const int lane = tid & 31;
    const int qb   = lane & ~3;

    for (int i = tid; i < RCT * 64; i += 256) h_s[0][i] = 0.f;
    if (tid < RCT) {
        const int t0 = dir ? (T - 1) : 0;
        x_s[0][tid] = *(const float4*)(x + ((long)(b0 + tid) * T + t0) * 4);
    }
    __syncthreads();

    float c[RCT];
    #pragma unroll
    for (int j = 0; j < RCT; j++) c[j] = 0.f;
    int p = 0;

    for (int s = 0; s < T; s++) {
        const int t = dir ? (T - 1 - s) : s;
        if (tid < RCT) {
            const int sn = (s + 1 < T) ? s + 1 : s;
            const int tn = dir ? (T - 1 - sn) : sn;
            x_s[p ^ 1][tid] = *(const float4*)(x + ((long)(b0 + tid) * T + tn) * 4);
        }

        float pre[RCT];
        #pragma unroll
        for (int j = 0; j < RCT; j++) {
            ULL a0 = 0, a1 = 0;
            const ulonglong2* h4 = (const ulonglong2*)(h_s[p] + j * 64);
            #pragma unroll
            for (int k = 0; k < 16; k++) {
                ulonglong2 hv = h4[k];
                ffma2(a0, w2[2 * k],     hv.x);
                ffma2(a1, w2[2 * k + 1], hv.y);
            }
            const float2 f0 = unpack2(a0), f1 = unpack2(a1);
            const float4 xv = x_s[p][j];
            pre[j] = f0.x + f0.y + f1.x + f1.y + bias
                   + wih.x * xv.x + wih.y * xv.y + wih.z * xv.z + wih.w * xv.w;
        }

        #pragma unroll
        for (int j = 0; j < RCT; j++) {
            const float act = (g == 2) ? tanh_ap(pre[j]) : sig_ap(pre[j]);
            const float iv = __shfl_sync(0xffffffffu, act, qb + 0);
            const float fv = __shfl_sync(0xffffffffu, act, qb + 1);
            const float gv = __shfl_sync(0xffffffffu, act, qb + 2);
            const float ov = __shfl_sync(0xffffffffu, act, qb + 3);
            c[j] = fmaf(fv, c[j], iv * gv);
            const float h = ov * tanh_ap(c[j]);
            if (g == 0) {
                h_s[p ^ 1][j * 64 + u] = h;
                g_h0h[((long)(b0 + j) * T + t) * 128 + dir * 64 + u] = bf16of(h);
            }
        }
        p ^= 1;
        __syncthreads();
    }
}

__global__ __launch_bounds__(256, 2) void lstm_l0(
    const float* __restrict__ x,
    const float* __restrict__ Wih_f, const float* __restrict__ Whh_f, const float* __restrict__ b_f,
    const float* __restrict__ Wih_b, const float* __restrict__ Whh_b, const float* __restrict__ b_b)
{
    __shared__ __align__(16) float h_s[2][4 * 64];
    __shared__ __align__(16) float4 x_s[2][4];

    const int xw  = blockIdx.x;
    const int dir = blockIdx.y;
    const bool big = map_big(xw, dir);
    const int b0   = map_b0(xw, dir, big);
    const int tid = threadIdx.x;

    const float* Wih = dir ? Wih_b : Wih_f;
    const float* Whh = dir ? Whh_b : Whh_f;
    const float* bb  = dir ? b_b   : b_f;

    if (big) l0_body<4>(dir, b0, tid, x, Wih, Whh, bb, h_s, x_s);
    else     l0_body<3>(dir, b0, tid, x, Wih, Whh, bb, h_s, x_s);
}

// =======================================================================
// Prep: g_Bth[n][k] = bf16(Wih_l1[n&255][k])   (n = dir*256 + gate_row)
// =======================================================================
__global__ void prep_bth(const float* __restrict__ Wf, const float* __restrict__ Wb)
{
    const int idx = blockIdx.x * 512 + threadIdx.x;   // 65536
    const int n = idx >> 7, k = idx & 127;
    const float* W = (n & 256) ? Wb : Wf;
    g_Bth[idx] = bf16of(W[(n & 255) * 128 + k]);
}

// =======================================================================
// xp1 GEMM via bf16 mma.sync.m16n8k16 (half the mma instructions of tf32 k8).
// A = g_h0h [m][k] bf16 (natural), B = g_Bth [n][k] bf16; both k-contiguous
// -> every fragment register is ONE lds.u32. Smem rows padded to KP=40 u16
// (bank map (20g+cc)%32: conflict-free). 3-stage cp.async, K = 4 slabs of 32.
// grid (4, 2048) n-fast, blk 256, 2 CTAs/SM (60KB smem/CTA).
// =======================================================================
constexpr int KP = 40;                         // u16 per smem row (32 used)
constexpr int SLAB_U16 = 128 * KP;             // one A or B slab
constexpr int STG_U16 = 2 * SLAB_U16;
constexpr int SMEM_GEMM = 3 * STG_U16 * 2;     // 61440 B

__global__ __launch_bounds__(256, 2) void gemm_xp1(
    const float* __restrict__ bias_f, const float* __restrict__ bias_b)
{
    extern __shared__ uint16_t smh[];   // [stage][{A,B}][128][KP]
    const uint32_t smB = (uint32_t)__cvta_generic_to_shared(smh);
    const int tid  = threadIdx.x;
    const int lane = tid & 31;
    const int wid  = tid >> 5;
    const int g    = lane >> 2;
    const int cc   = lane & 3;
    const int wm   = (wid & 3) * 32;
    const int wn   = (wid >> 2) * 64;
    const long m0 = (long)blockIdx.y * 128;
    const int  n0 = blockIdx.x * 128;

    float acc[2][8][4];
    #pragma unroll
    for (int i = 0; i < 2; i++)
        #pragma unroll
        for (int j = 0; j < 8; j++)
            #pragma unroll
            for (int q = 0; q < 4; q++) acc[i][j][q] = 0.f;

    // slab loader: 512 cp16 per operand; thread e covers (row = e>>2, part = e&3)
    auto load_slab = [&](int buf, int kc) {
        const uint32_t abase = smB + (uint32_t)(buf * STG_U16) * 2;
        const uint32_t bbase = abase + (uint32_t)SLAB_U16 * 2;
        #pragma unroll
        for (int i = 0; i < 2; i++) {
            const int e = tid + i * 256;
            const int r = e >> 2, pt = e & 3;
            cp16(abase + (uint32_t)(r * KP + pt * 8) * 2,
                 g_h0h + (m0 + r) * 128 + kc * 32 + pt * 8);
        }
        #pragma unroll
        for (int i = 0; i < 2; i++) {
            const int e = tid + i * 256;
            const int r = e >> 2, pt = e & 3;
            cp16(bbase + (uint32_t)(r * KP + pt * 8) * 2,
                 g_Bth + (long)(n0 + r) * 128 + kc * 32 + pt * 8);
        }
    };

    load_slab(0, 0); cp_commit();
    load_slab(1, 1); cp_commit();

    for (int kc = 0; kc < 4; kc++) {
        if (kc == 3) cp_wait0(); else cp_wait1();
        __syncthreads();
        if (kc + 2 < 4) { load_slab((kc + 2) % 3, kc + 2); cp_commit(); }

        const uint32_t* As = (const uint32_t*)(smh + (kc % 3) * STG_U16);   // row stride 20 u32
        const uint32_t* Bs = As + SLAB_U16 / 2;

        #pragma unroll
        for (int kk = 0; kk < 2; kk++) {
            const int ko = kk * 8 + cc;                 // u32 k-offset within row
            uint32_t a[2][4];
            #pragma unroll
            for (int i = 0; i < 2; i++) {
                const uint32_t* ap = As + (wm + 16 * i + g) * 20 + ko;
                a[i][0] = ap[0];            // (row g,     k 2cc..2cc+1)
                a[i][1] = ap[8 * 20];       // (row g+8)
                a[i][2] = ap[4];            // (row g,     k +8)
                a[i][3] = ap[8 * 20 + 4];   // (row g+8,   k +8)
            }
            uint32_t b[8][2];
            #pragma unroll
            for (int j = 0; j < 8; j++) {
                const uint32_t* bp = Bs + (wn + j * 8 + g) * 20 + ko;
                b[j][0] = bp[0];
                b[j][1] = bp[4];
            }
            #pragma unroll
            for (int i = 0; i < 2; i++)
                #pragma unroll
                for (int j = 0; j < 8; j++) {
                    asm("mma.sync.aligned.m16n8k16.row.col.f32.bf16.bf16.f32 "
                        "{%0,%1,%2,%3}, {%4,%5,%6,%7}, {%8,%9}, {%0,%1,%2,%3};"
                        : "+f"(acc[i][j][0]), "+f"(acc[i][j][1]),
                          "+f"(acc[i][j][2]), "+f"(acc[i][j][3])
                        : "r"(a[i][0]), "r"(a[i][1]), "r"(a[i][2]), "r"(a[i][3]),
                          "r"(b[j][0]), "r"(b[j][1]));
                }
        }
    }

    // epilogue: + bias, pack bf16x2, u32 stores (layout identical to R11/R12)
    const float* bp = (n0 & 256) ? bias_b : bias_f;
    float bn0[8], bn1[8];
    #pragma unroll
    for (int j = 0; j < 8; j++) {
        const int n = ((n0 & 255) + wn + 8 * j + cc * 2);
        bn0[j] = bp[n & 255];
        bn1[j] = bp[(n + 1) & 255];
    }
    #pragma unroll
    for (int i = 0; i < 2; i++) {
        const long mrow = m0 + wm + 16 * i + g;
        uint16_t* r0 = g_xp1h + mrow * 512;
        uint16_t* r1 = r0 + 8 * 512;
        #pragma unroll
        for (int j = 0; j < 8; j++) {
            const int n = n0 + wn + 8 * j + cc * 2;
            *(uint32_t*)(r0 + n) = bf16x2(acc[i][j][1] + bn1[j], acc[i][j][0] + bn0[j]);
            *(uint32_t*)(r1 + n) = bf16x2(acc[i][j][3] + bn1[j], acc[i][j][2] + bn0[j]);
        }
    }
}

// =======================================================================
// Layer-1 biLSTM core (R12-exact, PROTECTED), templated rows.
// =======================================================================
template <int RCT>
__device__ __forceinline__ void l1_body(
    int dir, int b0, int tid,
    const float* __restrict__ Whh,
    float (&h_s)[2][4 * 64], uint16_t (&xp_s)[2][4][4][72])
{
    const int u   = tid >> 2;
    const int g   = tid & 3;
    const int row = g * 64 + u;

    ULL w2[32];
    {
        const ULL* wp = (const ULL*)(Whh + row * 64);
        #pragma unroll
        for (int i = 0; i < 32; i++) w2[i] = wp[i];
    }
    const int lane = tid & 31;
    const int qb   = lane & ~3;

    const int j_st  = tid >> 6;
    const int c_st  = tid & 63;
    const int g_st  = c_st >> 4;
    const int u4_st = (c_st & 15) * 4;
    const uint32_t xpsB = (uint32_t)__cvta_generic_to_shared(&xp_s[0][0][0][0]);
    const uint32_t st_off = (uint32_t)(((j_st * 4 + g_st) * 72 + u4_st) * 2);
    const uint32_t buf_stride = (uint32_t)(4 * 4 * 72 * 2);
    const uint16_t* xp_src = g_xp1h + (long)(b0 + j_st) * T * 512 + dir * 256 + g_st * 64 + u4_st;
    const bool do_st = (j_st < RCT);

    for (int i = tid; i < RCT * 64; i += 256) h_s[0][i] = 0.f;

    float c[RCT], hsum[RCT];
    #pragma unroll
    for (int j = 0; j < RCT; j++) { c[j] = 0.f; hsum[j] = 0.f; }
    {
        const int t0 = dir ? (T - 1) : 0;
        if (do_st) cp8(xpsB + st_off, xp_src + (long)t0 * 512);
        cp_commit();
        cp_wait0();
    }
    __syncthreads();

    int p = 0;
    for (int s = 0; s < T; s++) {
        if (s + 1 < T) {
            const int tn = dir ? (T - 2 - s) : (s + 1);
            if (do_st) cp8(xpsB + (p ^ 1) * buf_stride + st_off, xp_src + (long)tn * 512);
            cp_commit();
        }

        float pre[RCT];
        #pragma unroll
        for (int j = 0; j < RCT; j++) {
            ULL a0 = 0, a1 = 0;
            const ulonglong2* h4 = (const ulonglong2*)(h_s[p] + j * 64);
            #pragma unroll
            for (int k = 0; k < 16; k++) {
                ulonglong2 hv = h4[k];
                ffma2(a0, w2[2 * k],     hv.x);
                ffma2(a1, w2[2 * k + 1], hv.y);
            }
            const float2 f0 = unpack2(a0), f1 = unpack2(a1);
            pre[j] = f0.x + f0.y + f1.x + f1.y + bf16_to_f32(xp_s[p][j][g][u]);
        }

        #pragma unroll
        for (int j = 0; j < RCT; j++) {
            const float act = (g == 2) ? tanh_ap(pre[j]) : sig_ap(pre[j]);
            const float iv = __shfl_sync(0xffffffffu, act, qb + 0);
            const float fv = __shfl_sync(0xffffffffu, act, qb + 1);
            const float gv = __shfl_sync(0xffffffffu, act, qb + 2);
            const float ov = __shfl_sync(0xffffffffu, act, qb + 3);
            c[j] = fmaf(fv, c[j], iv * gv);
            const float h = ov * tanh_ap(c[j]);
            hsum[j] += h;
            if (g == 0) h_s[p ^ 1][j * 64 + u] = h;
        }
        cp_wait0();
        p ^= 1;
        __syncthreads();
    }

    if (g == 0) {
        #pragma unroll
        for (int j = 0; j < RCT; j++)
            g_pooled[(b0 + j) * 128 + dir * 64 + u] = hsum[j];
    }
}

__global__ __launch_bounds__(256, 2) void lstm_l1(
    const float* __restrict__ Whh_f, const float* __restrict__ Whh_b)
{
    __shared__ __align__(16) float h_s[2][4 * 64];
    __shared__ __align__(16) uint16_t xp_s[2][4][4][72];

    const int xw  = blockIdx.x;
    const int dir = blockIdx.y;
    const bool big = map_big(xw, dir);
    const int b0   = map_b0(xw, dir, big);
    const int tid = threadIdx.x;
    const float* Whh = dir ? Whh_b : Whh_f;

    if (big) l1_body<4>(dir, b0, tid, Whh, h_s, xp_s);
    else     l1_body<3>(dir, b0, tid, Whh, h_s, xp_s);
}

// =======================================================================
__global__ void fc_kernel(const float* __restrict__ fcw, const float* __restrict__ fcb,
                          float* __restrict__ out)
{
    const int gw   = (blockIdx.x * blockDim.x + threadIdx.x) >> 5;
    const int lane = threadIdx.x & 31;
    if (gw >= B) return;
    float sum = 0.f;
    #pragma unroll
    for (int qq = 0; qq < 4; qq++)
        sum += g_pooled[gw * 128 + qq * 32 + lane] * fcw[qq * 32 + lane];
    #pragma unroll
    for (int o = 16; o; o >>= 1) sum += __shfl_xor_sync(0xffffffffu, sum, o);
    if (lane == 0) out[gw] = sum * (1.f / 512.f) + fcb[0];
}

// =======================================================================
extern "C" void kernel_launch(void* const* d_in, const int* in_sizes, int n_in,
                              void* d_out, int out_size)
{
    const float* x     = (const float*)d_in[0];
    const float* Wih0f = (const float*)d_in[1];
    const float* Whh0f = (const float*)d_in[2];
    const float* b0f   = (const float*)d_in[3];
    const float* Wih0b = (const float*)d_in[4];
    const float* Whh0b = (const float*)d_in[5];
    const float* b0b   = (const float*)d_in[6];
    const float* Wih1f = (const float*)d_in[7];
    const float* Whh1f = (const float*)d_in[8];
    const float* b1f   = (const float*)d_in[9];
    const float* Wih1b = (const float*)d_in[10];
    const float* Whh1b = (const float*)d_in[11];
    const float* b1b   = (const float*)d_in[12];
    const float* fcw   = (const float*)d_in[13];
    const float* fcb   = (const float*)d_in[14];

    prep_bth<<<128, 512>>>(Wih1f, Wih1b);
    lstm_l0<<<dim3(148, 2), 256>>>(x, Wih0f, Whh0f, b0f, Wih0b, Whh0b, b0b);
    cudaFuncSetAttribute(gemm_xp1, cudaFuncAttributeMaxDynamicSharedMemorySize, SMEM_GEMM);
    gemm_xp1<<<dim3(4, 2048), 256, SMEM_GEMM>>>(b1f, b1b);
    lstm_l1<<<dim3(148, 2), 256>>>(Whh1f, Whh1b);
    fc_kernel<<<32, 512>>>(fcw, fcb, (float*)d_out);
}